// round 5
// baseline (speedup 1.0000x reference)
#include <cuda_runtime.h>
#include <cstdint>

// Fixed problem shape
#define HH 128
#define WW 240
#define NG 40
#define CPG 8
#define DD 48
#define PADL 48
#define NPOS (WW + PADL)   // 288
#define ROWA 296           // 288 + skew headroom
#define TPB 128

#define GWC_BLOCKS (HH * NG)   // 5120
#define CAT_BLOCKS (24 * DD)   // 1152
#define MIX_LIMIT (CAT_BLOCKS * 5)   // 5760
#define TOTAL_BLOCKS (GWC_BLOCKS + CAT_BLOCKS)  // 6272

// skewed smem index: conflict-free for lane patterns p = 2*lane + const
__device__ __forceinline__ int swz(int p) { return p + (p >> 5); }

__global__ __launch_bounds__(TPB, 8)
void fused_kernel(const float* __restrict__ ref, const float* __restrict__ tgt,
                  const float* __restrict__ refc, const float* __restrict__ tgtc,
                  float* __restrict__ out) {
    __shared__ float s[CPG * ROWA];   // 9472 B

    const int bid = blockIdx.x;
    const int tid = threadIdx.x;

    // ---- interleave concat blocks among gwc blocks (overlap their DRAM) ----
    bool is_cat;
    int wid_;
    if (bid < MIX_LIMIT) {
        int q = bid / 5, r = bid - q * 5;
        is_cat = (r == 4);
        wid_ = is_cat ? q : (q * 4 + r);
    } else {
        is_cat = false;
        wid_ = 4 * CAT_BLOCKS + (bid - MIX_LIMIT);
    }

    if (!is_cat) {
        // ============ gwc block: one (h, group), 120 compute threads ============
        const int g = wid_ % NG;
        const int h = wid_ / NG;

        for (int i = tid; i < CPG * NPOS; i += TPB) {
            int k = i / NPOS, p = i - k * NPOS;
            float v = 0.0f;
            if (p >= PADL)
                v = tgt[(((size_t)(g * CPG + k)) * HH + h) * WW + (p - PADL)];
            s[k * ROWA + swz(p)] = v;
        }
        __syncthreads();

        if (tid < 120) {
            const int w2 = tid * 2;

            // ref channels (x 1/8 folded), 8 ch x 2 w  -> 16 regs
            float r[CPG][2];
#pragma unroll
            for (int k = 0; k < CPG; ++k) {
                float2 v = *(const float2*)(ref + (((size_t)(g * CPG + k)) * HH + h) * WW + w2);
                r[k][0] = v.x * 0.125f; r[k][1] = v.y * 0.125f;
            }

            // rolling window: slot = position parity
            float Wb[CPG][2];
            {
                const int p0 = PADL + w2;        // even -> slot 0
                const int i0 = swz(p0), i1 = swz(p0 + 1);
#pragma unroll
                for (int k = 0; k < CPG; ++k) {
                    Wb[k][0] = s[k * ROWA + i0];
                    Wb[k][1] = s[k * ROWA + i1];
                }
            }

            float* op = out + ((size_t)g * DD * HH + h) * WW + w2;

#pragma unroll 4
            for (int d2 = 0; d2 < DD; d2 += 2) {
                // ---- d = d2 (even): output j uses slot j ----
                {
                    float a0 = 0.f, b0 = 0.f, a1 = 0.f, b1 = 0.f;
#pragma unroll
                    for (int k = 0; k < 4; ++k) {
                        a0 += r[k][0]     * Wb[k][0];
                        b0 += r[k + 4][0] * Wb[k + 4][0];
                        a1 += r[k][1]     * Wb[k][1];
                        b1 += r[k + 4][1] * Wb[k + 4][1];
                    }
                    float2 o; o.x = a0 + b0; o.y = a1 + b1;
                    *(float2*)op = o;
                    op += HH * WW;
                    const int idx = swz(PADL + w2 - d2 - 1);   // parity 1 -> slot 1
#pragma unroll
                    for (int k = 0; k < CPG; ++k)
                        Wb[k][1] = s[k * ROWA + idx];
                }
                // ---- d = d2+1 (odd): output j uses slot j^1 ----
                {
                    float a0 = 0.f, b0 = 0.f, a1 = 0.f, b1 = 0.f;
#pragma unroll
                    for (int k = 0; k < 4; ++k) {
                        a0 += r[k][0]     * Wb[k][1];
                        b0 += r[k + 4][0] * Wb[k + 4][1];
                        a1 += r[k][1]     * Wb[k][0];
                        b1 += r[k + 4][1] * Wb[k + 4][0];
                    }
                    float2 o; o.x = a0 + b0; o.y = a1 + b1;
                    *(float2*)op = o;
                    op += HH * WW;
                    const int idx = swz(PADL + w2 - d2 - 2);   // parity 0 -> slot 0
#pragma unroll
                    for (int k = 0; k < CPG; ++k)
                        Wb[k][0] = s[k * ROWA + idx];
                }
            }
        }
    } else {
        // ============ concat block: one (c, d) plane, 120 threads ============
        const int d = wid_ % DD;
        const int c = wid_ / DD;          // 0..23
        if (tid >= 120) return;
        const int wq   = tid % 60;
        const int half = tid / 60;        // two h-halves of 64 rows each
        const int wb = wq * 4;
        const int h0 = half * 64;

        float* ob = out + ((((size_t)(NG + c) * DD + d) * HH) + h0) * WW + wb;
        const bool m0 = (wb + 0 >= d), m1 = (wb + 1 >= d),
                   m2 = (wb + 2 >= d), m3 = (wb + 3 >= d);

        if (c < 12) {
            const float* ib = refc + (((size_t)c * HH) + h0) * WW + wb;
#pragma unroll 4
            for (int h = 0; h < 64; ++h) {
                float4 x = *(const float4*)(ib + h * WW);
                float4 v;
                v.x = m0 ? x.x : 0.f;
                v.y = m1 ? x.y : 0.f;
                v.z = m2 ? x.z : 0.f;
                v.w = m3 ? x.w : 0.f;
                *(float4*)(ob + h * WW) = v;
            }
        } else {
            const float* ib = tgtc + (((size_t)(c - 12) * HH) + h0) * WW + (wb - d);
#pragma unroll 4
            for (int h = 0; h < 64; ++h) {
                const float* p = ib + h * WW;
                float4 v;
                v.x = m0 ? __ldg(p + 0) : 0.f;
                v.y = m1 ? __ldg(p + 1) : 0.f;
                v.z = m2 ? __ldg(p + 2) : 0.f;
                v.w = m3 ? __ldg(p + 3) : 0.f;
                *(float4*)(ob + h * WW) = v;
            }
        }
    }
}

extern "C" void kernel_launch(void* const* d_in, const int* in_sizes, int n_in,
                              void* d_out, int out_size) {
    const float* ref_gwc    = (const float*)d_in[0];
    const float* tgt_gwc    = (const float*)d_in[1];
    const float* ref_concat = (const float*)d_in[2];
    const float* tgt_concat = (const float*)d_in[3];
    float* out = (float*)d_out;

    fused_kernel<<<TOTAL_BLOCKS, TPB>>>(ref_gwc, tgt_gwc, ref_concat, tgt_concat, out);
}

// round 6
// speedup vs baseline: 1.0310x; 1.0310x over previous
#include <cuda_runtime.h>
#include <cstdint>

// Fixed problem shape
#define HH 128
#define WW 240
#define NG 40
#define CPG 8
#define DD 48
#define PADL 48
#define NPOS (WW + PADL)   // 288 positions per row
#define ROWA 305           // odd stride: k-half pairs land on disjoint bank classes
#define TPB 128

#define GWC_BLOCKS (HH * NG)   // 5120
#define CAT_BLOCKS (24 * DD)   // 1152
#define MIX_LIMIT (CAT_BLOCKS * 5)   // 5760
#define TOTAL_BLOCKS (GWC_BLOCKS + CAT_BLOCKS)  // 6272

// x2 skew: lane pattern p = P + 4q maps 16 lanes to 16 distinct (even-class) banks
__device__ __forceinline__ int swz(int p) { return p + 2 * (p >> 5); }

__global__ __launch_bounds__(TPB, 8)
void fused_kernel(const float* __restrict__ ref, const float* __restrict__ tgt,
                  const float* __restrict__ refc, const float* __restrict__ tgtc,
                  float* __restrict__ out) {
    __shared__ float s[CPG * ROWA];   // 9760 B

    const int bid = blockIdx.x;
    const int tid = threadIdx.x;

    // ---- interleave concat blocks among gwc blocks ----
    bool is_cat;
    int wid_;
    if (bid < MIX_LIMIT) {
        int q5 = bid / 5, r5 = bid - q5 * 5;
        is_cat = (r5 == 4);
        wid_ = is_cat ? q5 : (q5 * 4 + r5);
    } else {
        is_cat = false;
        wid_ = 4 * CAT_BLOCKS + (bid - MIX_LIMIT);
    }

    if (!is_cat) {
        // ========== gwc block: one (h, group); lane pairs split channels ==========
        const int g = wid_ % NG;
        const int h = wid_ / NG;

        // fill smem: channel c -> row 2*(c&3) + (c>>2), skewed, left zero pad
        for (int i = tid; i < CPG * NPOS; i += TPB) {
            int c = i / NPOS, p = i - c * NPOS;
            float v = 0.0f;
            if (p >= PADL)
                v = tgt[(((size_t)(g * CPG + c)) * HH + h) * WW + (p - PADL)];
            int row = 2 * (c & 3) + (c >> 2);
            s[row * ROWA + swz(p)] = v;
        }
        __syncthreads();

        const int kh = tid & 1;           // channel half: 0 -> ch 0..3, 1 -> ch 4..7
        int q = tid >> 1;                 // w-quad id
        const bool active = (q < 60);
        if (q > 59) q = 59;               // clamp so full warps stay converged for shfl
        const int w4 = q * 4;

        // ref: 4 channels x 4 w (x 1/8 folded)  -> 16 regs
        float r[4][4];
#pragma unroll
        for (int k = 0; k < 4; ++k) {
            const int c = kh * 4 + k;
            float4 v = *(const float4*)(ref + (((size_t)(g * CPG + c)) * HH + h) * WW + w4);
            r[k][0] = v.x * 0.125f; r[k][1] = v.y * 0.125f;
            r[k][2] = v.z * 0.125f; r[k][3] = v.w * 0.125f;
        }

        // smem row base for this thread's 4 channels: row(c) = 2k + kh
        // rolling window: Wb[k][slot], slot = position & 3
        float Wb[4][4];
#pragma unroll
        for (int k = 0; k < 4; ++k) {
            const int rb = (2 * k + kh) * ROWA;
#pragma unroll
            for (int j = 0; j < 4; ++j)
                Wb[k][j] = s[rb + swz(PADL + w4 + j)];
        }

        float* op = out + ((size_t)g * DD * HH + h) * WW + w4 + 2 * kh;

        for (int d4 = 0; d4 < DD; d4 += 4) {
#pragma unroll
            for (int t = 0; t < 4; ++t) {
                const int d = d4 + t;
                float a0 = 0.f, a1 = 0.f, a2 = 0.f, a3 = 0.f;
#pragma unroll
                for (int k = 0; k < 4; ++k) {
                    a0 += r[k][0] * Wb[k][(0 + 4 - t) & 3];
                    a1 += r[k][1] * Wb[k][(1 + 4 - t) & 3];
                    a2 += r[k][2] * Wb[k][(2 + 4 - t) & 3];
                    a3 += r[k][3] * Wb[k][(3 + 4 - t) & 3];
                }
                // pair exchange: kh=0 needs partner's a0,a1; kh=1 needs partner's a2,a3
                float v0 = kh ? a0 : a2;
                float v1 = kh ? a1 : a3;
                float u0 = __shfl_xor_sync(0xffffffffu, v0, 1);
                float u1 = __shfl_xor_sync(0xffffffffu, v1, 1);
                if (active) {
                    float2 o;
                    if (kh == 0) { o.x = a0 + u0; o.y = a1 + u1; }
                    else         { o.x = a2 + u0; o.y = a3 + u1; }
                    *(float2*)op = o;
                }
                op += HH * WW;

                // slide window: new position w4 - d - 1 -> slot (3 - t) & 3
                const int sp = swz(PADL + w4 - d - 1);
#pragma unroll
                for (int k = 0; k < 4; ++k)
                    Wb[k][(3 + 4 - t) & 3] = s[(2 * k + kh) * ROWA + sp];
            }
        }
    } else {
        // ========== concat block: one (c, d) plane, 120 threads ==========
        const int d = wid_ % DD;
        const int c = wid_ / DD;          // 0..23
        if (tid >= 120) return;
        const int wq   = tid % 60;
        const int half = tid / 60;
        const int wb = wq * 4;
        const int h0 = half * 64;

        float* ob = out + ((((size_t)(NG + c) * DD + d) * HH) + h0) * WW + wb;
        const bool m0 = (wb + 0 >= d), m1 = (wb + 1 >= d),
                   m2 = (wb + 2 >= d), m3 = (wb + 3 >= d);

        if (c < 12) {
            const float* ib = refc + (((size_t)c * HH) + h0) * WW + wb;
#pragma unroll 4
            for (int h = 0; h < 64; ++h) {
                float4 x = *(const float4*)(ib + h * WW);
                float4 v;
                v.x = m0 ? x.x : 0.f;
                v.y = m1 ? x.y : 0.f;
                v.z = m2 ? x.z : 0.f;
                v.w = m3 ? x.w : 0.f;
                *(float4*)(ob + h * WW) = v;
            }
        } else {
            const float* ib = tgtc + (((size_t)(c - 12) * HH) + h0) * WW + (wb - d);
#pragma unroll 4
            for (int h = 0; h < 64; ++h) {
                const float* p = ib + h * WW;
                float4 v;
                v.x = m0 ? __ldg(p + 0) : 0.f;
                v.y = m1 ? __ldg(p + 1) : 0.f;
                v.z = m2 ? __ldg(p + 2) : 0.f;
                v.w = m3 ? __ldg(p + 3) : 0.f;
                *(float4*)(ob + h * WW) = v;
            }
        }
    }
}

extern "C" void kernel_launch(void* const* d_in, const int* in_sizes, int n_in,
                              void* d_out, int out_size) {
    const float* ref_gwc    = (const float*)d_in[0];
    const float* tgt_gwc    = (const float*)d_in[1];
    const float* ref_concat = (const float*)d_in[2];
    const float* tgt_concat = (const float*)d_in[3];
    float* out = (float*)d_out;

    fused_kernel<<<TOTAL_BLOCKS, TPB>>>(ref_gwc, tgt_gwc, ref_concat, tgt_concat, out);
}

// round 7
// speedup vs baseline: 1.3341x; 1.2939x over previous
#include <cuda_runtime.h>
#include <cstdint>

// Fixed problem shape
#define HH 128
#define WW 240
#define NG 40
#define CPG 8
#define DD 48
#define PADL 48
#define NPOS (WW + PADL)   // 288 positions per smem row
#define ROWA 292           // stride ≡ 4 (mod 8): kh halves hit disjoint bank sets
#define TPB 128

#define GWC_BLOCKS (HH * NG)   // 5120
#define CAT_BLOCKS (24 * DD)   // 1152
#define MIX_LIMIT (CAT_BLOCKS * 5)   // 5760
#define TOTAL_BLOCKS (GWC_BLOCKS + CAT_BLOCKS)  // 6272

__device__ __forceinline__ void stcs4(float* p, float4 v) { __stcs((float4*)p, v); }
__device__ __forceinline__ void stcs2(float* p, float2 v) { __stcs((float2*)p, v); }

__global__ __launch_bounds__(TPB, 8)
void fused_kernel(const float* __restrict__ ref, const float* __restrict__ tgt,
                  const float* __restrict__ refc, const float* __restrict__ tgtc,
                  float* __restrict__ out) {
    __shared__ float s[CPG * ROWA];   // 9344 B

    const int bid = blockIdx.x;
    const int tid = threadIdx.x;

    bool is_cat;
    int wid_;
    if (bid < MIX_LIMIT) {
        int q5 = bid / 5, r5 = bid - q5 * 5;
        is_cat = (r5 == 4);
        wid_ = is_cat ? q5 : (q5 * 4 + r5);
    } else {
        is_cat = false;
        wid_ = 4 * CAT_BLOCKS + (bid - MIX_LIMIT);
    }

    if (!is_cat) {
        // ======== gwc block: one (h, group); lane pairs split channels ========
        const int g = wid_ % NG;
        const int h = wid_ / NG;

        // fill smem rows (row = channel, stride 292, left zero pad), float4 path
        for (int i = tid; i < CPG * (NPOS / 4); i += TPB) {
            const int c = i / (NPOS / 4), j = i - c * (NPOS / 4);
            const int p4 = j * 4;
            float4 v;
            if (p4 >= PADL)
                v = *(const float4*)(tgt + (((size_t)(g * CPG + c)) * HH + h) * WW + (p4 - PADL));
            else
                v = make_float4(0.f, 0.f, 0.f, 0.f);
            *(float4*)(s + c * ROWA + p4) = v;
        }
        __syncthreads();

        const int kh = tid & 1;            // 0 -> channels 0..3, 1 -> channels 4..7
        int q = tid >> 1;                  // w-quad id 0..63
        const bool active = (q < 60);
        if (q > 59) q = 59;                // keep warps converged for shfl
        const int w4 = q * 4;

        // ref: 4 channels x 4 w, x1/8 folded  (16 regs)
        float r[4][4];
#pragma unroll
        for (int k = 0; k < 4; ++k) {
            const int c = kh * 4 + k;
            float4 v = *(const float4*)(ref + (((size_t)(g * CPG + c)) * HH + h) * WW + w4);
            r[k][0] = v.x * 0.125f; r[k][1] = v.y * 0.125f;
            r[k][2] = v.z * 0.125f; r[k][3] = v.w * 0.125f;
        }

        // two position-quads per channel; rows for this thread: c = 4*kh + k
        const float* srow[4];
#pragma unroll
        for (int k = 0; k < 4; ++k) srow[k] = s + (kh * 4 + k) * ROWA;

        float4 A[4], B[4];                 // rolling quads (32 regs)
        // init "hi" buffer B = positions [w4 .. w4+3]
#pragma unroll
        for (int k = 0; k < 4; ++k) B[k] = *(const float4*)(srow[k] + PADL + w4);

        int pb = PADL + w4 - 4;            // quad-aligned, >= 0 for all groups
        float* op = out + ((size_t)g * DD * HH + h) * WW + w4 + 2 * kh;

        // one disparity step: lo = positions pb.., hi = positions pb+4..
        // out j at d = d0+t uses flattened F[4 + j - t] (F = [lo|hi])
#define GWC_STEP(LO, HI, T)                                                     \
        {                                                                       \
            float a0 = 0.f, a1 = 0.f, a2 = 0.f, a3 = 0.f;                       \
            _Pragma("unroll")                                                   \
            for (int k = 0; k < 4; ++k) {                                       \
                const float F[8] = { LO[k].x, LO[k].y, LO[k].z, LO[k].w,        \
                                     HI[k].x, HI[k].y, HI[k].z, HI[k].w };      \
                a0 += r[k][0] * F[4 + 0 - (T)];                                 \
                a1 += r[k][1] * F[4 + 1 - (T)];                                 \
                a2 += r[k][2] * F[4 + 2 - (T)];                                 \
                a3 += r[k][3] * F[4 + 3 - (T)];                                 \
            }                                                                   \
            float v0 = kh ? a0 : a2;                                            \
            float v1 = kh ? a1 : a3;                                            \
            float u0 = __shfl_xor_sync(0xffffffffu, v0, 1);                     \
            float u1 = __shfl_xor_sync(0xffffffffu, v1, 1);                     \
            if (active) {                                                       \
                float2 o;                                                       \
                if (kh == 0) { o.x = a0 + u0; o.y = a1 + u1; }                  \
                else         { o.x = a2 + u0; o.y = a3 + u1; }                  \
                stcs2(op, o);                                                   \
            }                                                                   \
            op += HH * WW;                                                      \
        }

#pragma unroll
        for (int dp = 0; dp < DD / 8; ++dp) {
            // group A: lo = A (new), hi = B
#pragma unroll
            for (int k = 0; k < 4; ++k) A[k] = *(const float4*)(srow[k] + pb);
            GWC_STEP(A, B, 0) GWC_STEP(A, B, 1) GWC_STEP(A, B, 2) GWC_STEP(A, B, 3)
            pb -= 4;
            // group B: lo = B (new), hi = A
#pragma unroll
            for (int k = 0; k < 4; ++k) B[k] = *(const float4*)(srow[k] + pb);
            GWC_STEP(B, A, 0) GWC_STEP(B, A, 1) GWC_STEP(B, A, 2) GWC_STEP(B, A, 3)
            pb -= 4;
        }
#undef GWC_STEP
    } else {
        // ======== concat block: one (c, d) plane, 120 threads ========
        const int d = wid_ % DD;
        const int c = wid_ / DD;
        if (tid >= 120) return;
        const int wq   = tid % 60;
        const int half = tid / 60;
        const int wb = wq * 4;
        const int h0 = half * 64;

        float* ob = out + ((((size_t)(NG + c) * DD + d) * HH) + h0) * WW + wb;
        const bool m0 = (wb + 0 >= d), m1 = (wb + 1 >= d),
                   m2 = (wb + 2 >= d), m3 = (wb + 3 >= d);

        if (c < 12) {
            const float* ib = refc + (((size_t)c * HH) + h0) * WW + wb;
#pragma unroll 4
            for (int h = 0; h < 64; ++h) {
                float4 x = *(const float4*)(ib + h * WW);
                float4 v;
                v.x = m0 ? x.x : 0.f;
                v.y = m1 ? x.y : 0.f;
                v.z = m2 ? x.z : 0.f;
                v.w = m3 ? x.w : 0.f;
                stcs4(ob + h * WW, v);
            }
        } else {
            const float* ib = tgtc + (((size_t)(c - 12) * HH) + h0) * WW + (wb - d);
#pragma unroll 4
            for (int h = 0; h < 64; ++h) {
                const float* p = ib + h * WW;
                float4 v;
                v.x = m0 ? __ldg(p + 0) : 0.f;
                v.y = m1 ? __ldg(p + 1) : 0.f;
                v.z = m2 ? __ldg(p + 2) : 0.f;
                v.w = m3 ? __ldg(p + 3) : 0.f;
                stcs4(ob + h * WW, v);
            }
        }
    }
}

extern "C" void kernel_launch(void* const* d_in, const int* in_sizes, int n_in,
                              void* d_out, int out_size) {
    const float* ref_gwc    = (const float*)d_in[0];
    const float* tgt_gwc    = (const float*)d_in[1];
    const float* ref_concat = (const float*)d_in[2];
    const float* tgt_concat = (const float*)d_in[3];
    float* out = (float*)d_out;

    fused_kernel<<<TOTAL_BLOCKS, TPB>>>(ref_gwc, tgt_gwc, ref_concat, tgt_concat, out);
}